// round 10
// baseline (speedup 1.0000x reference)
#include <cuda_runtime.h>
#include <cuda_fp16.h>
#include <math.h>
#include <stdint.h>

// Problem dims
#define M_TOT 8192
#define D_DIM 256
#define BD    2700
#define NC    1024
#define KPAD  2752          // 86 * 32
#define NFG   1280          // NC + D_DIM
#define EPS_ENT 1e-8f

// ---------------------------------------------------------------------------
__device__ __forceinline__ uint32_t smem_to_u32(const void* p) {
    uint32_t a;
    asm("{ .reg .u64 t; cvta.to.shared.u64 t, %1; cvt.u32.u64 %0, t; }" : "=r"(a) : "l"(p));
    return a;
}
__device__ __forceinline__ unsigned short f2h(float x) {
    unsigned short r;
    asm("cvt.rn.f16.f32 %0, %1;" : "=h"(r) : "f"(x));
    return r;
}
__device__ __forceinline__ float h2f(unsigned short h) {
    float f;
    asm("cvt.f32.f16 %0, %1;" : "=f"(f) : "h"(h));
    return f;
}
#define LDSM_X4(R, addr) \
    asm volatile("ldmatrix.sync.aligned.m8n8.x4.shared.b16 {%0,%1,%2,%3}, [%4];" \
        : "=r"((R)[0]), "=r"((R)[1]), "=r"((R)[2]), "=r"((R)[3]) : "r"(addr))

__device__ __forceinline__ void mma16816(float* c, const uint32_t* a, const uint32_t* b) {
    asm volatile("mma.sync.aligned.m16n8k16.row.col.f32.f16.f16.f32 "
        "{%0,%1,%2,%3}, {%4,%5,%6,%7}, {%8,%9}, {%0,%1,%2,%3};"
        : "+f"(c[0]), "+f"(c[1]), "+f"(c[2]), "+f"(c[3])
        : "r"(a[0]), "r"(a[1]), "r"(a[2]), "r"(a[3]), "r"(b[0]), "r"(b[1]));
}
__device__ __forceinline__ void cp16(uint32_t dst, const void* src) {
    asm volatile("cp.async.cg.shared.global [%0], [%1], 16;" :: "r"(dst), "l"(src) : "memory");
}
#define CP_COMMIT() asm volatile("cp.async.commit_group;" ::: "memory")

// ---------------------------------------------------------------------------
// Scratch (device globals)
// ---------------------------------------------------------------------------
__device__ __align__(16) unsigned short g_ehi[(size_t)NC * KPAD];
__device__ __align__(16) unsigned short g_elo[(size_t)NC * KPAD];
__device__ __align__(16) unsigned short g_wthi[(size_t)D_DIM * KPAD];
__device__ __align__(16) unsigned short g_wtlo[(size_t)D_DIM * KPAD];
__device__ __align__(16) unsigned short g_sfhi[(size_t)M_TOT * D_DIM];
__device__ __align__(16) unsigned short g_sflo[(size_t)M_TOT * D_DIM];
__device__ __align__(16) unsigned short g_sfThi[(size_t)D_DIM * M_TOT];  // sf^T
__device__ __align__(16) unsigned short g_sfTlo[(size_t)D_DIM * M_TOT];
__device__ __align__(16) float g_FG[(size_t)NFG * D_DIM];                // [F; G]
__device__ __align__(16) float g_C[(size_t)D_DIM * D_DIM];               // sf^T sf
// B fragments for gS: [ntile 160][chunk 4][kq 4][lane 32] -> uint2
__device__ __align__(16) uint2 g_Bfh[160 * 4 * 4 * 32];
__device__ __align__(16) uint2 g_Bfl[160 * 4 * 4 * 32];
__device__ __align__(16) float g_dist[(size_t)M_TOT * NC];
__device__ __align__(16) float g_ecoef[NC];
__device__ __align__(16) float g_h[D_DIM];
__device__ __align__(16) float g_sfcol_part[32][D_DIM];   // overwrite partials
__device__ __align__(16) float g_znG_part[64];            // overwrite partials
__device__ float g_colsum[NC];
__device__ float g_vqsum;
__device__ float g_bnorm;
__device__ unsigned int g_ticket;

// ===========================================================================
// PREP kernel roles:
//  [0,1280)      zero FG          [1280,1536)  zero C
//  [1536,2560)   prep_E           [2560,4608)  split sf
//  [4608,5296)   prep_W           [5296,7344)  transpose sf -> sfT hi/lo
//  [7344,7376)   sfcol partials   [7376]       misc zero + bnorm
// ===========================================================================
#define PREP_ZFG_END   1280
#define PREP_ZC_END    1536
#define PREP_E_END     2560
#define PREP_SF_END    4608
#define PREP_W_END     5296
#define PREP_SFT_END   7344
#define PREP_COL_END   7376
#define PREP_BLOCKS    7377

__global__ void __launch_bounds__(256) k_prep(const float* __restrict__ E,
                                              const float* __restrict__ b,
                                              const float* __restrict__ sf,
                                              const float* __restrict__ W) {
    const int bid = blockIdx.x;
    const int tid = threadIdx.x;

    if (bid < PREP_ZFG_END) {
        g_FG[bid * 256 + tid] = 0.f;
        return;
    }
    if (bid < PREP_ZC_END) {
        g_C[(bid - PREP_ZFG_END) * 256 + tid] = 0.f;
        return;
    }
    if (bid < PREP_E_END) {
        const int row = bid - PREP_ZC_END;
        const float4* src = (const float4*)(E + (size_t)row * BD);
        const float4* b4 = (const float4*)b;
        uint2* dh = (uint2*)(g_ehi + (size_t)row * KPAD);
        uint2* dl = (uint2*)(g_elo + (size_t)row * KPAD);
        float s = 0.f, s2 = 0.f;
        for (int i = tid; i < BD / 4; i += 256) {
            float4 v = src[i];
            float4 bv = b4[i];
            s  += v.x * v.x + v.y * v.y + v.z * v.z + v.w * v.w;
            s2 += v.x * bv.x + v.y * bv.y + v.z * bv.z + v.w * bv.w;
            unsigned short h0 = f2h(v.x), h1 = f2h(v.y), h2 = f2h(v.z), h3 = f2h(v.w);
            unsigned short l0 = f2h(v.x - h2f(h0)), l1 = f2h(v.y - h2f(h1));
            unsigned short l2 = f2h(v.z - h2f(h2)), l3 = f2h(v.w - h2f(h3));
            uint2 uh, ul;
            uh.x = (uint32_t)h0 | ((uint32_t)h1 << 16); uh.y = (uint32_t)h2 | ((uint32_t)h3 << 16);
            ul.x = (uint32_t)l0 | ((uint32_t)l1 << 16); ul.y = (uint32_t)l2 | ((uint32_t)l3 << 16);
            dh[i] = uh; dl[i] = ul;
        }
        __shared__ float sw[8], sw2[8];
        for (int o = 16; o > 0; o >>= 1) {
            s  += __shfl_down_sync(0xffffffffu, s, o);
            s2 += __shfl_down_sync(0xffffffffu, s2, o);
        }
        int lane = tid & 31, w = tid >> 5;
        if (lane == 0) { sw[w] = s; sw2[w] = s2; }
        __syncthreads();
        if (w == 0) {
            s  = (lane < 8) ? sw[lane] : 0.f;
            s2 = (lane < 8) ? sw2[lane] : 0.f;
            for (int o = 4; o > 0; o >>= 1) {
                s  += __shfl_down_sync(0xffffffffu, s, o);
                s2 += __shfl_down_sync(0xffffffffu, s2, o);
            }
            if (lane == 0) g_ecoef[row] = s - 2.f * s2;
        }
        return;
    }
    if (bid < PREP_SF_END) {
        int idx = (bid - PREP_E_END) * 256 + tid;
        float4 v = ((const float4*)sf)[idx];
        unsigned short h0 = f2h(v.x), h1 = f2h(v.y), h2 = f2h(v.z), h3 = f2h(v.w);
        unsigned short l0 = f2h(v.x - h2f(h0)), l1 = f2h(v.y - h2f(h1));
        unsigned short l2 = f2h(v.z - h2f(h2)), l3 = f2h(v.w - h2f(h3));
        uint2 uh, ul;
        uh.x = (uint32_t)h0 | ((uint32_t)h1 << 16); uh.y = (uint32_t)h2 | ((uint32_t)h3 << 16);
        ul.x = (uint32_t)l0 | ((uint32_t)l1 << 16); ul.y = (uint32_t)l2 | ((uint32_t)l3 << 16);
        ((uint2*)g_sfhi)[idx] = uh;
        ((uint2*)g_sflo)[idx] = ul;
        return;
    }
    if (bid < PREP_W_END) {
        __shared__ float tile[32][33];
        const int l = bid - PREP_SF_END;
        const int d0 = (l & 7) * 32, n0 = (l >> 3) * 32;
        const int tx = tid & 31, ty = tid >> 5;
#pragma unroll
        for (int i = 0; i < 4; i++) {
            int n = n0 + ty + i * 8;
            tile[ty + i * 8][tx] = (n < BD) ? W[(size_t)n * D_DIM + d0 + tx] : 0.f;
        }
        __syncthreads();
#pragma unroll
        for (int i = 0; i < 4; i++) {
            int d = d0 + ty + i * 8;
            int n = n0 + tx;
            float v = tile[tx][ty + i * 8];
            unsigned short h = f2h(v);
            g_wthi[(size_t)d * KPAD + n] = h;
            g_wtlo[(size_t)d * KPAD + n] = f2h(v - h2f(h));
        }
        return;
    }
    if (bid < PREP_SFT_END) {
        // transpose sf [8192,256] -> sfT [256,8192] hi/lo; 32x32 tiles
        __shared__ float tile[32][33];
        const int l = bid - PREP_W_END;       // 0..2047
        const int d0 = (l & 7) * 32, m0 = (l >> 3) * 32;
        const int tx = tid & 31, ty = tid >> 5;
#pragma unroll
        for (int i = 0; i < 4; i++) {
            int m = m0 + ty + i * 8;
            tile[ty + i * 8][tx] = sf[(size_t)m * D_DIM + d0 + tx];
        }
        __syncthreads();
#pragma unroll
        for (int i = 0; i < 4; i++) {
            int d = d0 + ty + i * 8;
            int m = m0 + tx;
            float v = tile[tx][ty + i * 8];
            unsigned short h = f2h(v);
            g_sfThi[(size_t)d * M_TOT + m] = h;
            g_sfTlo[(size_t)d * M_TOT + m] = f2h(v - h2f(h));
        }
        return;
    }
    if (bid < PREP_COL_END) {
        // sfcol partials: block j sums sf over m in [j*256, j*256+256), thread=d
        const int j = bid - PREP_SFT_END;
        float s = 0.f;
        const float* base = sf + (size_t)j * 256 * D_DIM + tid;
        for (int m = 0; m < 256; m++) s += base[(size_t)m * D_DIM];
        g_sfcol_part[j][tid] = s;
        return;
    }
    {
#pragma unroll
        for (int i = 0; i < 4; i++) g_colsum[tid + i * 256] = 0.f;
        g_h[tid] = 0.f;
        if (tid == 0) { g_vqsum = 0.f; g_ticket = 0u; }
        float s = 0.f;
        for (int i = tid; i < BD; i += 256) { float bv = b[i]; s += bv * bv; }
        __shared__ float sw[8];
        for (int o = 16; o > 0; o >>= 1) s += __shfl_down_sync(0xffffffffu, s, o);
        int lane = tid & 31, w = tid >> 5;
        if (lane == 0) sw[w] = s;
        __syncthreads();
        if (w == 0) {
            s = (lane < 8) ? sw[lane] : 0.f;
            for (int o = 4; o > 0; o >>= 1) s += __shfl_down_sync(0xffffffffu, s, o);
            if (lane == 0) g_bnorm = s;
        }
    }
}

// ---------------------------------------------------------------------------
// fg mainloop (B in smem, K-chunk 32, 3-stage, 4-pass)
// ---------------------------------------------------------------------------
#define STAGE_FG 32768
#define SMEM_FG  (3 * STAGE_FG)

__device__ __forceinline__ void fg_mainloop(
    const unsigned short* __restrict__ Ahi, const unsigned short* __restrict__ Alo, int ldA,
    const unsigned short* __restrict__ Bhi, const unsigned short* __restrict__ Blo, int ldB,
    int m0, int n0, int kbeg, int kend, uint32_t sb0, float (&acc)[4][4][4])
{
    const int tid = threadIdx.x;
    const int lane = tid & 31, wid = tid >> 5;
    const int wm = (wid & 1) * 64;
    const int wn = (wid >> 1) * 32;
    const int nch = kend - kbeg;

    auto issue = [&](int c, int s) {
        const int k0 = c * 32;
        const uint32_t sb = sb0 + s * STAGE_FG;
#pragma unroll
        for (int t = 0; t < 2; t++) {
            int u = t * 256 + tid;
            int r = u >> 2, c8 = u & 3;
            uint32_t off = r * 64 + ((c8 ^ ((r >> 1) & 3)) << 4);
            cp16(sb + off,         Ahi + (size_t)(m0 + r) * ldA + k0 + c8 * 8);
            cp16(sb + off + 8192,  Alo + (size_t)(m0 + r) * ldA + k0 + c8 * 8);
            cp16(sb + off + 16384, Bhi + (size_t)(n0 + r) * ldB + k0 + c8 * 8);
            cp16(sb + off + 24576, Blo + (size_t)(n0 + r) * ldB + k0 + c8 * 8);
        }
        CP_COMMIT();
    };

    issue(kbeg, 0);
    if (nch > 1) issue(kbeg + 1, 1);
    int s = 0;
    for (int c = kbeg; c < kend; c++) {
        if (c + 1 < kend) asm volatile("cp.async.wait_group 1;" ::: "memory");
        else              asm volatile("cp.async.wait_group 0;" ::: "memory");
        __syncthreads();
        if (c + 2 < kend) {
            int s2 = s + 2; if (s2 >= 3) s2 -= 3;
            issue(c + 2, s2);
        }
        const uint32_t sb = sb0 + s * STAGE_FG;
#pragma unroll
        for (int kb = 0; kb < 2; kb++) {
            uint32_t ah[4][4], al[4][4], bh[8], bl[8];
#pragma unroll
            for (int mt = 0; mt < 4; mt++) {
                int row = wm + mt * 16 + (lane & 15);
                int c8 = kb * 2 + (lane >> 4);
                uint32_t a = sb + row * 64 + ((c8 ^ ((row >> 1) & 3)) << 4);
                LDSM_X4(ah[mt], a);
                LDSM_X4(al[mt], a + 8192);
            }
#pragma unroll
            for (int nb = 0; nb < 2; nb++) {
                int rn = wn + nb * 16 + (lane & 7) + ((lane >> 4) << 3);
                int c8 = kb * 2 + ((lane >> 3) & 1);
                uint32_t baddr = sb + 16384 + rn * 64 + ((c8 ^ ((rn >> 1) & 3)) << 4);
                LDSM_X4(bh + nb * 4, baddr);
                LDSM_X4(bl + nb * 4, baddr + 8192);
            }
#pragma unroll
            for (int mt = 0; mt < 4; mt++)
#pragma unroll
                for (int n8 = 0; n8 < 4; n8++)
                    mma16816(acc[mt][n8], ah[mt], bh + n8 * 2);
#pragma unroll
            for (int mt = 0; mt < 4; mt++)
#pragma unroll
                for (int n8 = 0; n8 < 4; n8++)
                    mma16816(acc[mt][n8], ah[mt], bl + n8 * 2);
#pragma unroll
            for (int mt = 0; mt < 4; mt++)
#pragma unroll
                for (int n8 = 0; n8 < 4; n8++)
                    mma16816(acc[mt][n8], al[mt], bh + n8 * 2);
#pragma unroll
            for (int mt = 0; mt < 4; mt++)
#pragma unroll
                for (int n8 = 0; n8 < 4; n8++)
                    mma16816(acc[mt][n8], al[mt], bl + n8 * 2);
        }
        s++; if (s >= 3) s -= 3;
        __syncthreads();
    }
}

#define ACC_DECL float acc[4][4][4]; \
    _Pragma("unroll") for (int a_ = 0; a_ < 4; a_++) \
    _Pragma("unroll") for (int b_ = 0; b_ < 4; b_++) \
    _Pragma("unroll") for (int c_ = 0; c_ < 4; c_++) acc[a_][b_][c_] = 0.f;

// ===========================================================================
// gFG kernel roles:
//  [0,240)    F = E@W       [240,412) G = W^T W
//  [412,476)  C = sfT sfT^T [476,645) h = W^T b
// ===========================================================================
#define GFG_F_END 240
#define GFG_G_END 412
#define GFG_C_END 476
#define GFG_BLOCKS 645

__global__ void __launch_bounds__(256, 2) gFG_kernel(const float* __restrict__ W,
                                                     const float* __restrict__ b) {
    const int bid = blockIdx.x;
    if (bid >= GFG_C_END) {
        const int tid = threadIdx.x;
        const int n0 = (bid - GFG_C_END) * 16;
        float hacc = 0.f;
        for (int r = 0; r < 16; r++) {
            int n = n0 + r;
            if (n < BD) hacc += __ldg(b + n) * W[(size_t)n * D_DIM + tid];
        }
        atomicAdd(&g_h[tid], hacc);
        return;
    }
    extern __shared__ char smem[];
    uint32_t sb0 = smem_to_u32(smem);
    ACC_DECL;
    const int lane = threadIdx.x & 31, wid = threadIdx.x >> 5;
    const int wm = (wid & 1) * 64, wn = (wid >> 1) * 32;
    const int g = lane >> 2, t = lane & 3;

    int m0, n0, kbeg, kend, ld;
    const unsigned short *Ah, *Al, *Bh, *Bl;
    float* outbase;
    if (bid < GFG_F_END) {
        m0 = (bid / 30) * 128;
        int rem = bid % 30;
        n0 = (rem / 15) * 128;
        kbeg = (rem % 15) * 6;
        kend = kbeg + 6; if (kend > 86) kend = 86;
        Ah = g_ehi; Al = g_elo; Bh = g_wthi; Bl = g_wtlo; ld = KPAD;
        outbase = g_FG;
    } else if (bid < GFG_G_END) {
        int l = bid - GFG_F_END;
        m0 = (l / 86) * 128;
        int rem = l % 86;
        n0 = (rem / 43) * 128;
        kbeg = (rem % 43) * 2;
        kend = kbeg + 2;
        Ah = g_wthi; Al = g_wtlo; Bh = g_wthi; Bl = g_wtlo; ld = KPAD;
        outbase = g_FG + (size_t)NC * D_DIM;
    } else {
        int l = bid - GFG_G_END;          // 0..63
        int q = l >> 4;                    // 0..3
        m0 = (q & 1) * 128;
        n0 = (q >> 1) * 128;
        kbeg = (l & 15) * 16;
        kend = kbeg + 16;
        Ah = g_sfThi; Al = g_sfTlo; Bh = g_sfThi; Bl = g_sfTlo; ld = M_TOT;
        outbase = g_C;
    }
    fg_mainloop(Ah, Al, ld, Bh, Bl, ld, m0, n0, kbeg, kend, sb0, acc);
#pragma unroll
    for (int mt = 0; mt < 4; mt++)
#pragma unroll
        for (int n8 = 0; n8 < 4; n8++) {
            int col = n0 + wn + n8 * 8 + t * 2;
#pragma unroll
            for (int h = 0; h < 2; h++) {
                int m = m0 + wm + mt * 16 + g + h * 8;
                atomicAdd(&outbase[(size_t)m * D_DIM + col],     acc[mt][n8][h * 2 + 0]);
                atomicAdd(&outbase[(size_t)m * D_DIM + col + 1], acc[mt][n8][h * 2 + 1]);
            }
        }
}

// ===========================================================================
// splitFG: [0,320) pack F rows -> B fragments hi/lo; [320,384) <C,G> partials
// ===========================================================================
__global__ void __launch_bounds__(256) k_splitFG() {
    const int bid = blockIdx.x;
    const int tid = threadIdx.x;
    if (bid >= 320) {
        // <C,G> partial: block handles 1024 elements
        const int base = (bid - 320) * 1024;
        const float* Gm = g_FG + (size_t)NC * D_DIM;
        float s = 0.f;
#pragma unroll
        for (int i = 0; i < 4; i++) {
            int e = base + tid + i * 256;
            s += g_C[e] * Gm[e];
        }
        __shared__ float sw[8];
        for (int o = 16; o > 0; o >>= 1) s += __shfl_down_sync(0xffffffffu, s, o);
        int lane = tid & 31, w = tid >> 5;
        if (lane == 0) sw[w] = s;
        __syncthreads();
        if (w == 0) {
            s = (lane < 8) ? sw[lane] : 0.f;
            for (int o = 4; o > 0; o >>= 1) s += __shfl_down_sync(0xffffffffu, s, o);
            if (lane == 0) g_znG_part[bid - 320] = s;
        }
        return;
    }
    int idx = bid * 256 + tid;     // [0, 81920)
    int lane = idx & 31;
    int kq = (idx >> 5) & 3;
    int chunk = (idx >> 7) & 3;
    int ntile = idx >> 9;
    int n = ntile * 8 + (lane >> 2);
    int kb = chunk * 64 + kq * 16 + (lane & 3) * 2;
    const float* Fr = g_FG + (size_t)n * D_DIM + kb;
    float2 v0 = *(const float2*)Fr;
    float2 v1 = *(const float2*)(Fr + 8);
    unsigned short h00 = f2h(v0.x), h01 = f2h(v0.y);
    unsigned short h10 = f2h(v1.x), h11 = f2h(v1.y);
    unsigned short l00 = f2h(v0.x - h2f(h00)), l01 = f2h(v0.y - h2f(h01));
    unsigned short l10 = f2h(v1.x - h2f(h10)), l11 = f2h(v1.y - h2f(h11));
    uint2 uh, ul;
    uh.x = (uint32_t)h00 | ((uint32_t)h01 << 16);
    uh.y = (uint32_t)h10 | ((uint32_t)h11 << 16);
    ul.x = (uint32_t)l00 | ((uint32_t)l01 << 16);
    ul.y = (uint32_t)l10 | ((uint32_t)l11 << 16);
    g_Bfh[idx] = uh;
    g_Bfl[idx] = ul;
}

// ===========================================================================
// gS kernel: A in smem (K-chunk 64, 3-stage), B from fragment gmem.
// grid (8, 64): dist only (P eliminated)
// ===========================================================================
#define STAGE_S 32768
#define SMEM_S  (3 * STAGE_S)

__global__ void __launch_bounds__(256, 2) gS_kernel() {
    extern __shared__ char smem[];
    uint32_t sb0 = smem_to_u32(smem);
    ACC_DECL;
    const int tid = threadIdx.x;
    const int lane = tid & 31, wid = tid >> 5;
    const int wm = (wid & 1) * 64, wn = (wid >> 1) * 32;
    const int m0 = blockIdx.y * 128, n0 = blockIdx.x * 128;
    const int bntile = (n0 + wn) >> 3;

    auto issueA = [&](int c, int s) {
        const int k0 = c * 64;
        const uint32_t sb = sb0 + s * STAGE_S;
#pragma unroll
        for (int t = 0; t < 4; t++) {
            int u = t * 256 + tid;
            int r = u >> 3, c8 = u & 7;
            uint32_t off = r * 128 + ((c8 ^ (r & 7)) << 4);
            cp16(sb + off,         g_sfhi + (size_t)(m0 + r) * D_DIM + k0 + c8 * 8);
            cp16(sb + off + 16384, g_sflo + (size_t)(m0 + r) * D_DIM + k0 + c8 * 8);
        }
        CP_COMMIT();
    };

    issueA(0, 0);
    issueA(1, 1);
    int s = 0;
    for (int c = 0; c < 4; c++) {
        if (c < 3) asm volatile("cp.async.wait_group 1;" ::: "memory");
        else       asm volatile("cp.async.wait_group 0;" ::: "memory");
        __syncthreads();
        if (c + 2 < 4) {
            int s2 = s + 2; if (s2 >= 3) s2 -= 3;
            issueA(c + 2, s2);
        }
        const uint32_t sb = sb0 + s * STAGE_S;
#pragma unroll
        for (int kq = 0; kq < 4; kq++) {
            uint32_t ah[4][4], al[4][4], bh[8], bl[8];
#pragma unroll
            for (int mt = 0; mt < 4; mt++) {
                int row = wm + mt * 16 + (lane & 15);
                int c8 = kq * 2 + (lane >> 4);
                uint32_t a = sb + row * 128 + ((c8 ^ (row & 7)) << 4);
                LDSM_X4(ah[mt], a);
                LDSM_X4(al[mt], a + 16384);
            }
#pragma unroll
            for (int n8 = 0; n8 < 4; n8++) {
                size_t bi = (((size_t)(bntile + n8) * 4 + c) * 4 + kq) * 32 + lane;
                uint2 h2 = g_Bfh[bi];
                uint2 l2 = g_Bfl[bi];
                bh[n8 * 2] = h2.x; bh[n8 * 2 + 1] = h2.y;
                bl[n8 * 2] = l2.x; bl[n8 * 2 + 1] = l2.y;
            }
#pragma unroll
            for (int mt = 0; mt < 4; mt++)
#pragma unroll
                for (int n8 = 0; n8 < 4; n8++)
                    mma16816(acc[mt][n8], ah[mt], bh + n8 * 2);
#pragma unroll
            for (int mt = 0; mt < 4; mt++)
#pragma unroll
                for (int n8 = 0; n8 < 4; n8++)
                    mma16816(acc[mt][n8], ah[mt], bl + n8 * 2);
#pragma unroll
            for (int mt = 0; mt < 4; mt++)
#pragma unroll
                for (int n8 = 0; n8 < 4; n8++)
                    mma16816(acc[mt][n8], al[mt], bh + n8 * 2);
        }
        s++; if (s >= 3) s -= 3;
        __syncthreads();
    }

    const int g = lane >> 2, t = lane & 3;
#pragma unroll
    for (int mt = 0; mt < 4; mt++)
#pragma unroll
        for (int n8 = 0; n8 < 4; n8++) {
            int col = n0 + wn + n8 * 8 + t * 2;
            float2 ec = *(const float2*)(g_ecoef + col);
#pragma unroll
            for (int h = 0; h < 2; h++) {
                int m = m0 + wm + mt * 16 + g + h * 8;
                float2 o;
                o.x = ec.x - 2.f * acc[mt][n8][h * 2 + 0];
                o.y = ec.y - 2.f * acc[mt][n8][h * 2 + 1];
                *(float2*)(g_dist + (size_t)m * NC + col) = o;
            }
        }
}

// ===========================================================================
// rowz: 1024 blocks: argmin + softmax + colsum + dmin + gather.
// Last block computes final scalars (vq_loss via <C,G> + sfcol.h + M*bnorm).
// ===========================================================================
__global__ void __launch_bounds__(256) k_rowz(float* __restrict__ out_idx,
                                              const float* __restrict__ E,
                                              float* __restrict__ out) {
    const int bid = blockIdx.x;
    const int tid = threadIdx.x, lane = tid & 31, w = tid >> 5;
    __shared__ float swv[8];
    __shared__ int   swi[8];
    __shared__ float s_min, s_sum;
    __shared__ int   sidx[8];
    float cs0 = 0.f, cs1 = 0.f, cs2 = 0.f, cs3 = 0.f;
    float dmin_sum = 0.f;
    const int r0 = bid * 8;
    for (int rr = 0; rr < 8; rr++) {
        const int row = r0 + rr;
        float4 v = ((const float4*)(g_dist + (size_t)row * NC))[tid];
        float vmin = v.x; int imin = tid * 4;
        if (v.y < vmin) { vmin = v.y; imin = tid * 4 + 1; }
        if (v.z < vmin) { vmin = v.z; imin = tid * 4 + 2; }
        if (v.w < vmin) { vmin = v.w; imin = tid * 4 + 3; }
        for (int o = 16; o > 0; o >>= 1) {
            float ov = __shfl_down_sync(0xffffffffu, vmin, o);
            int   oi = __shfl_down_sync(0xffffffffu, imin, o);
            if (ov < vmin || (ov == vmin && oi < imin)) { vmin = ov; imin = oi; }
        }
        if (lane == 0) { swv[w] = vmin; swi[w] = imin; }
        __syncthreads();
        if (w == 0) {
            vmin = (lane < 8) ? swv[lane] : 3.4e38f;
            imin = (lane < 8) ? swi[lane] : 0x7fffffff;
            for (int o = 4; o > 0; o >>= 1) {
                float ov = __shfl_down_sync(0xffffffffu, vmin, o);
                int   oi = __shfl_down_sync(0xffffffffu, imin, o);
                if (ov < vmin || (ov == vmin && oi < imin)) { vmin = ov; imin = oi; }
            }
            if (lane == 0) {
                s_min = vmin;
                sidx[rr] = imin;
                out_idx[row] = (float)imin;
            }
        }
        __syncthreads();
        const float mn = s_min;
        if (tid == 0) dmin_sum += mn;
        float e0 = expf(mn - v.x), e1 = expf(mn - v.y);
        float e2 = expf(mn - v.z), e3 = expf(mn - v.w);
        float ss = e0 + e1 + e2 + e3;
        for (int o = 16; o > 0; o >>= 1) ss += __shfl_down_sync(0xffffffffu, ss, o);
        if (lane == 0) swv[w] = ss;
        __syncthreads();
        if (w == 0) {
            ss = (lane < 8) ? swv[lane] : 0.f;
            for (int o = 4; o > 0; o >>= 1) ss += __shfl_down_sync(0xffffffffu, ss, o);
            if (lane == 0) s_sum = ss;
        }
        __syncthreads();
        const float inv = 1.f / s_sum;
        cs0 += e0 * inv; cs1 += e1 * inv; cs2 += e2 * inv; cs3 += e3 * inv;
        __syncthreads();
    }
    atomicAdd(&g_colsum[tid * 4 + 0], cs0);
    atomicAdd(&g_colsum[tid * 4 + 1], cs1);
    atomicAdd(&g_colsum[tid * 4 + 2], cs2);
    atomicAdd(&g_colsum[tid * 4 + 3], cs3);
    if (tid == 0) atomicAdd(&g_vqsum, dmin_sum);
    // gather q_st = E[idx] for the 8 rows
    for (int rr = 0; rr < 8; rr++) {
        const float4* e4 = (const float4*)(E + (size_t)sidx[rr] * BD);
        float4* o4 = (float4*)(out + (size_t)(r0 + rr) * BD);
        for (int i = tid; i < BD / 4; i += 256) o4[i] = e4[i];
    }

    // ---- last-block final scalars ----
    __shared__ unsigned int s_t;
    __threadfence();
    __syncthreads();
    if (tid == 0) s_t = atomicAdd(&g_ticket, 1u);
    __syncthreads();
    if (s_t == 1023u) {
        __threadfence();
        // entropy
        float t = 0.f;
#pragma unroll
        for (int i = 0; i < 4; i++) {
            float avg = g_colsum[tid + i * 256] * (1.0f / (float)M_TOT);
            t += -avg * logf(avg + EPS_ENT);
        }
        // znorm pieces: thread d: sfcol_d * h_d ; threads < 64 add znG parts
        float scd = 0.f;
#pragma unroll
        for (int j = 0; j < 32; j++) scd += g_sfcol_part[j][tid];
        float zn = 2.f * scd * g_h[tid];
        if (tid < 64) zn += g_znG_part[tid];
        __shared__ float sw[8], sw2[8];
        for (int o = 16; o > 0; o >>= 1) {
            t  += __shfl_down_sync(0xffffffffu, t, o);
            zn += __shfl_down_sync(0xffffffffu, zn, o);
        }
        if (lane == 0) { sw[w] = t; sw2[w] = zn; }
        __syncthreads();
        if (w == 0) {
            t  = (lane < 8) ? sw[lane] : 0.f;
            zn = (lane < 8) ? sw2[lane] : 0.f;
            for (int o = 4; o > 0; o >>= 1) {
                t  += __shfl_down_sync(0xffffffffu, t, o);
                zn += __shfl_down_sync(0xffffffffu, zn, o);
            }
            if (lane == 0) {
                const size_t OFF = (size_t)M_TOT * BD + M_TOT;
                float vq = g_vqsum + zn + (float)M_TOT * g_bnorm;
                out[OFF]     = vq * (1.0f / ((float)M_TOT * (float)BD));
                out[OFF + 1] = t;
            }
        }
    }
}

// ---------------------------------------------------------------------------
extern "C" void kernel_launch(void* const* d_in, const int* in_sizes, int n_in,
                              void* d_out, int out_size) {
    const float* sf = (const float*)d_in[0];
    const float* W  = (const float*)d_in[1];
    const float* b  = (const float*)d_in[2];
    const float* E  = (const float*)d_in[3];
    float* out      = (float*)d_out;
    float* out_idx  = out + (size_t)M_TOT * BD;

    cudaFuncSetAttribute(gFG_kernel, cudaFuncAttributeMaxDynamicSharedMemorySize, SMEM_FG);
    cudaFuncSetAttribute(gS_kernel,  cudaFuncAttributeMaxDynamicSharedMemorySize, SMEM_S);

    k_prep<<<PREP_BLOCKS, 256>>>(E, b, sf, W);
    gFG_kernel<<<GFG_BLOCKS, 256, SMEM_FG>>>(W, b);
    k_splitFG<<<384, 256>>>();
    gS_kernel<<<dim3(8, 64), 256, SMEM_S>>>();
    k_rowz<<<1024, 256>>>(out_idx, E, out);
}

// round 11
// speedup vs baseline: 1.2824x; 1.2824x over previous
#include <cuda_runtime.h>
#include <cuda_fp16.h>
#include <math.h>
#include <stdint.h>

// Problem dims
#define M_TOT 8192
#define D_DIM 256
#define BD    2700
#define NC    1024
#define KPAD  2752          // 86 * 32
#define NFG   1280          // NC + D_DIM
#define EPS_ENT 1e-8f

// ---------------------------------------------------------------------------
__device__ __forceinline__ uint32_t smem_to_u32(const void* p) {
    uint32_t a;
    asm("{ .reg .u64 t; cvta.to.shared.u64 t, %1; cvt.u32.u64 %0, t; }" : "=r"(a) : "l"(p));
    return a;
}
__device__ __forceinline__ unsigned short f2h(float x) {
    unsigned short r;
    asm("cvt.rn.f16.f32 %0, %1;" : "=h"(r) : "f"(x));
    return r;
}
__device__ __forceinline__ float h2f(unsigned short h) {
    float f;
    asm("cvt.f32.f16 %0, %1;" : "=f"(f) : "h"(h));
    return f;
}
#define LDSM_X4(R, addr) \
    asm volatile("ldmatrix.sync.aligned.m8n8.x4.shared.b16 {%0,%1,%2,%3}, [%4];" \
        : "=r"((R)[0]), "=r"((R)[1]), "=r"((R)[2]), "=r"((R)[3]) : "r"(addr))

__device__ __forceinline__ void mma16816(float* c, const uint32_t* a, const uint32_t* b) {
    asm volatile("mma.sync.aligned.m16n8k16.row.col.f32.f16.f16.f32 "
        "{%0,%1,%2,%3}, {%4,%5,%6,%7}, {%8,%9}, {%0,%1,%2,%3};"
        : "+f"(c[0]), "+f"(c[1]), "+f"(c[2]), "+f"(c[3])
        : "r"(a[0]), "r"(a[1]), "r"(a[2]), "r"(a[3]), "r"(b[0]), "r"(b[1]));
}
__device__ __forceinline__ void cp16(uint32_t dst, const void* src) {
    asm volatile("cp.async.cg.shared.global [%0], [%1], 16;" :: "r"(dst), "l"(src) : "memory");
}
#define CP_COMMIT() asm volatile("cp.async.commit_group;" ::: "memory")

// ---------------------------------------------------------------------------
// Scratch (device globals)
// ---------------------------------------------------------------------------
__device__ __align__(16) unsigned short g_ehi[(size_t)NC * KPAD];
__device__ __align__(16) unsigned short g_elo[(size_t)NC * KPAD];
__device__ __align__(16) unsigned short g_wthi[(size_t)D_DIM * KPAD];
__device__ __align__(16) unsigned short g_wtlo[(size_t)D_DIM * KPAD];
__device__ __align__(16) unsigned short g_sfhi[(size_t)M_TOT * D_DIM];
__device__ __align__(16) unsigned short g_sflo[(size_t)M_TOT * D_DIM];
__device__ __align__(16) float g_FG[(size_t)NFG * D_DIM];
// B fragments for gS: [ntile 160][chunk 4][kq 4][lane 32] -> uint2
__device__ __align__(16) uint2 g_Bfh[160 * 4 * 4 * 32];
__device__ __align__(16) uint2 g_Bfl[160 * 4 * 4 * 32];
__device__ __align__(16) float g_P[(size_t)M_TOT * D_DIM];
__device__ __align__(16) float g_dist[(size_t)M_TOT * NC];
__device__ __align__(16) float g_ecoef[NC];
__device__ __align__(16) float g_h[D_DIM];
__device__ float g_colsum[NC];
__device__ float g_vqsum;
__device__ float g_bnorm;
__device__ unsigned int g_ticket;

// ===========================================================================
// PREP kernel (R9 roles)
// ===========================================================================
#define PREP_ZERO_END  1280
#define PREP_E_END     2304
#define PREP_SF_END    4352
#define PREP_W_END     5040
#define PREP_BLOCKS    5041

__global__ void __launch_bounds__(256) k_prep(const float* __restrict__ E,
                                              const float* __restrict__ b,
                                              const float* __restrict__ sf,
                                              const float* __restrict__ W) {
    const int bid = blockIdx.x;
    const int tid = threadIdx.x;

    if (bid < PREP_ZERO_END) {
        g_FG[bid * 256 + tid] = 0.f;
        return;
    }
    if (bid < PREP_E_END) {
        const int row = bid - PREP_ZERO_END;
        const float4* src = (const float4*)(E + (size_t)row * BD);
        const float4* b4 = (const float4*)b;
        uint2* dh = (uint2*)(g_ehi + (size_t)row * KPAD);
        uint2* dl = (uint2*)(g_elo + (size_t)row * KPAD);
        float s = 0.f, s2 = 0.f;
        for (int i = tid; i < BD / 4; i += 256) {
            float4 v = src[i];
            float4 bv = b4[i];
            s  += v.x * v.x + v.y * v.y + v.z * v.z + v.w * v.w;
            s2 += v.x * bv.x + v.y * bv.y + v.z * bv.z + v.w * bv.w;
            unsigned short h0 = f2h(v.x), h1 = f2h(v.y), h2 = f2h(v.z), h3 = f2h(v.w);
            unsigned short l0 = f2h(v.x - h2f(h0)), l1 = f2h(v.y - h2f(h1));
            unsigned short l2 = f2h(v.z - h2f(h2)), l3 = f2h(v.w - h2f(h3));
            uint2 uh, ul;
            uh.x = (uint32_t)h0 | ((uint32_t)h1 << 16); uh.y = (uint32_t)h2 | ((uint32_t)h3 << 16);
            ul.x = (uint32_t)l0 | ((uint32_t)l1 << 16); ul.y = (uint32_t)l2 | ((uint32_t)l3 << 16);
            dh[i] = uh; dl[i] = ul;
        }
        __shared__ float sw[8], sw2[8];
        for (int o = 16; o > 0; o >>= 1) {
            s  += __shfl_down_sync(0xffffffffu, s, o);
            s2 += __shfl_down_sync(0xffffffffu, s2, o);
        }
        int lane = tid & 31, w = tid >> 5;
        if (lane == 0) { sw[w] = s; sw2[w] = s2; }
        __syncthreads();
        if (w == 0) {
            s  = (lane < 8) ? sw[lane] : 0.f;
            s2 = (lane < 8) ? sw2[lane] : 0.f;
            for (int o = 4; o > 0; o >>= 1) {
                s  += __shfl_down_sync(0xffffffffu, s, o);
                s2 += __shfl_down_sync(0xffffffffu, s2, o);
            }
            if (lane == 0) g_ecoef[row] = s - 2.f * s2;
        }
        return;
    }
    if (bid < PREP_SF_END) {
        int idx = (bid - PREP_E_END) * 256 + tid;
        float4 v = ((const float4*)sf)[idx];
        unsigned short h0 = f2h(v.x), h1 = f2h(v.y), h2 = f2h(v.z), h3 = f2h(v.w);
        unsigned short l0 = f2h(v.x - h2f(h0)), l1 = f2h(v.y - h2f(h1));
        unsigned short l2 = f2h(v.z - h2f(h2)), l3 = f2h(v.w - h2f(h3));
        uint2 uh, ul;
        uh.x = (uint32_t)h0 | ((uint32_t)h1 << 16); uh.y = (uint32_t)h2 | ((uint32_t)h3 << 16);
        ul.x = (uint32_t)l0 | ((uint32_t)l1 << 16); ul.y = (uint32_t)l2 | ((uint32_t)l3 << 16);
        ((uint2*)g_sfhi)[idx] = uh;
        ((uint2*)g_sflo)[idx] = ul;
        return;
    }
    if (bid < PREP_W_END) {
        __shared__ float tile[32][33];
        const int l = bid - PREP_SF_END;
        const int d0 = (l & 7) * 32, n0 = (l >> 3) * 32;
        const int tx = tid & 31, ty = tid >> 5;
#pragma unroll
        for (int i = 0; i < 4; i++) {
            int n = n0 + ty + i * 8;
            tile[ty + i * 8][tx] = (n < BD) ? W[(size_t)n * D_DIM + d0 + tx] : 0.f;
        }
        __syncthreads();
#pragma unroll
        for (int i = 0; i < 4; i++) {
            int d = d0 + ty + i * 8;
            int n = n0 + tx;
            float v = tile[tx][ty + i * 8];
            unsigned short h = f2h(v);
            g_wthi[(size_t)d * KPAD + n] = h;
            g_wtlo[(size_t)d * KPAD + n] = f2h(v - h2f(h));
        }
        return;
    }
    {
#pragma unroll
        for (int i = 0; i < 4; i++) g_colsum[tid + i * 256] = 0.f;
        g_h[tid] = 0.f;
        if (tid == 0) { g_vqsum = 0.f; g_ticket = 0u; }
        float s = 0.f;
        for (int i = tid; i < BD; i += 256) { float bv = b[i]; s += bv * bv; }
        __shared__ float sw[8];
        for (int o = 16; o > 0; o >>= 1) s += __shfl_down_sync(0xffffffffu, s, o);
        int lane = tid & 31, w = tid >> 5;
        if (lane == 0) sw[w] = s;
        __syncthreads();
        if (w == 0) {
            s = (lane < 8) ? sw[lane] : 0.f;
            for (int o = 4; o > 0; o >>= 1) s += __shfl_down_sync(0xffffffffu, s, o);
            if (lane == 0) g_bnorm = s;
        }
    }
}

// ---------------------------------------------------------------------------
// gFG mainloop (B in smem, K-chunk 32, 3-stage, 3-pass: hh + hl + lh)
// ---------------------------------------------------------------------------
#define STAGE_FG 32768
#define SMEM_FG  (3 * STAGE_FG)

__device__ __forceinline__ void fg_mainloop(
    const unsigned short* __restrict__ Ahi, const unsigned short* __restrict__ Alo,
    const unsigned short* __restrict__ Bhi, const unsigned short* __restrict__ Blo,
    int m0, int n0, int kbeg, int kend, uint32_t sb0, float (&acc)[4][4][4])
{
    const int tid = threadIdx.x;
    const int lane = tid & 31, wid = tid >> 5;
    const int wm = (wid & 1) * 64;
    const int wn = (wid >> 1) * 32;
    const int nch = kend - kbeg;

    auto issue = [&](int c, int s) {
        const int k0 = c * 32;
        const uint32_t sb = sb0 + s * STAGE_FG;
#pragma unroll
        for (int t = 0; t < 2; t++) {
            int u = t * 256 + tid;
            int r = u >> 2, c8 = u & 3;
            uint32_t off = r * 64 + ((c8 ^ ((r >> 1) & 3)) << 4);
            cp16(sb + off,         Ahi + (size_t)(m0 + r) * KPAD + k0 + c8 * 8);
            cp16(sb + off + 8192,  Alo + (size_t)(m0 + r) * KPAD + k0 + c8 * 8);
            cp16(sb + off + 16384, Bhi + (size_t)(n0 + r) * KPAD + k0 + c8 * 8);
            cp16(sb + off + 24576, Blo + (size_t)(n0 + r) * KPAD + k0 + c8 * 8);
        }
        CP_COMMIT();
    };

    issue(kbeg, 0);
    if (nch > 1) issue(kbeg + 1, 1);
    int s = 0;
    for (int c = kbeg; c < kend; c++) {
        if (c + 1 < kend) asm volatile("cp.async.wait_group 1;" ::: "memory");
        else              asm volatile("cp.async.wait_group 0;" ::: "memory");
        __syncthreads();
        if (c + 2 < kend) {
            int s2 = s + 2; if (s2 >= 3) s2 -= 3;
            issue(c + 2, s2);
        }
        const uint32_t sb = sb0 + s * STAGE_FG;
#pragma unroll
        for (int kb = 0; kb < 2; kb++) {
            uint32_t ah[4][4], al[4][4], bh[8], bl[8];
#pragma unroll
            for (int mt = 0; mt < 4; mt++) {
                int row = wm + mt * 16 + (lane & 15);
                int c8 = kb * 2 + (lane >> 4);
                uint32_t a = sb + row * 64 + ((c8 ^ ((row >> 1) & 3)) << 4);
                LDSM_X4(ah[mt], a);
                LDSM_X4(al[mt], a + 8192);
            }
#pragma unroll
            for (int nb = 0; nb < 2; nb++) {
                int rn = wn + nb * 16 + (lane & 7) + ((lane >> 4) << 3);
                int c8 = kb * 2 + ((lane >> 3) & 1);
                uint32_t baddr = sb + 16384 + rn * 64 + ((c8 ^ ((rn >> 1) & 3)) << 4);
                LDSM_X4(bh + nb * 4, baddr);
                LDSM_X4(bl + nb * 4, baddr + 8192);
            }
#pragma unroll
            for (int mt = 0; mt < 4; mt++)
#pragma unroll
                for (int n8 = 0; n8 < 4; n8++)
                    mma16816(acc[mt][n8], ah[mt], bh + n8 * 2);
#pragma unroll
            for (int mt = 0; mt < 4; mt++)
#pragma unroll
                for (int n8 = 0; n8 < 4; n8++)
                    mma16816(acc[mt][n8], ah[mt], bl + n8 * 2);
#pragma unroll
            for (int mt = 0; mt < 4; mt++)
#pragma unroll
                for (int n8 = 0; n8 < 4; n8++)
                    mma16816(acc[mt][n8], al[mt], bh + n8 * 2);
        }
        s++; if (s >= 3) s -= 3;
        __syncthreads();
    }
}

#define ACC_DECL4 float acc[4][4][4]; \
    _Pragma("unroll") for (int a_ = 0; a_ < 4; a_++) \
    _Pragma("unroll") for (int b_ = 0; b_ < 4; b_++) \
    _Pragma("unroll") for (int c_ = 0; c_ < 4; c_++) acc[a_][b_][c_] = 0.f;

// ===========================================================================
// gFG kernel
// ===========================================================================
#define GFG_F_END 240
#define GFG_G_END 412
#define GFG_BLOCKS 581

__global__ void __launch_bounds__(256, 2) gFG_kernel(const float* __restrict__ W,
                                                     const float* __restrict__ b) {
    const int bid = blockIdx.x;
    if (bid >= GFG_G_END) {
        const int tid = threadIdx.x;
        const int n0 = (bid - GFG_G_END) * 16;
        float hacc = 0.f;
        for (int r = 0; r < 16; r++) {
            int n = n0 + r;
            if (n < BD) hacc += __ldg(b + n) * W[(size_t)n * D_DIM + tid];
        }
        atomicAdd(&g_h[tid], hacc);
        return;
    }
    extern __shared__ char smem[];
    uint32_t sb0 = smem_to_u32(smem);
    ACC_DECL4;
    const int lane = threadIdx.x & 31, wid = threadIdx.x >> 5;
    const int wm = (wid & 1) * 64, wn = (wid >> 1) * 32;
    const int g = lane >> 2, t = lane & 3;

    int m0, n0, kbeg, kend;
    const unsigned short *Ah, *Al;
    float* outbase;
    if (bid < GFG_F_END) {
        m0 = (bid / 30) * 128;
        int rem = bid % 30;
        n0 = (rem / 15) * 128;
        kbeg = (rem % 15) * 6;
        kend = kbeg + 6; if (kend > 86) kend = 86;
        Ah = g_ehi; Al = g_elo;
        outbase = g_FG;
    } else {
        int l = bid - GFG_F_END;
        m0 = (l / 86) * 128;
        int rem = l % 86;
        n0 = (rem / 43) * 128;
        kbeg = (rem % 43) * 2;
        kend = kbeg + 2;
        Ah = g_wthi; Al = g_wtlo;
        outbase = g_FG + (size_t)NC * D_DIM;
    }
    fg_mainloop(Ah, Al, g_wthi, g_wtlo, m0, n0, kbeg, kend, sb0, acc);
#pragma unroll
    for (int mt = 0; mt < 4; mt++)
#pragma unroll
        for (int n8 = 0; n8 < 4; n8++) {
            int col = n0 + wn + n8 * 8 + t * 2;
#pragma unroll
            for (int h = 0; h < 2; h++) {
                int m = m0 + wm + mt * 16 + g + h * 8;
                atomicAdd(&outbase[(size_t)m * D_DIM + col],     acc[mt][n8][h * 2 + 0]);
                atomicAdd(&outbase[(size_t)m * D_DIM + col + 1], acc[mt][n8][h * 2 + 1]);
            }
        }
}

// ===========================================================================
// splitFG: pack FG fp32 -> mma B-fragment layout (hi/lo fp16)
// ===========================================================================
__global__ void __launch_bounds__(256) k_splitFG() {
    int idx = blockIdx.x * 256 + threadIdx.x;     // [0, 81920)
    int lane = idx & 31;
    int kq = (idx >> 5) & 3;
    int chunk = (idx >> 7) & 3;
    int ntile = idx >> 9;
    int n = ntile * 8 + (lane >> 2);
    int kb = chunk * 64 + kq * 16 + (lane & 3) * 2;
    const float* Fr = g_FG + (size_t)n * D_DIM + kb;
    float2 v0 = *(const float2*)Fr;
    float2 v1 = *(const float2*)(Fr + 8);
    unsigned short h00 = f2h(v0.x), h01 = f2h(v0.y);
    unsigned short h10 = f2h(v1.x), h11 = f2h(v1.y);
    unsigned short l00 = f2h(v0.x - h2f(h00)), l01 = f2h(v0.y - h2f(h01));
    unsigned short l10 = f2h(v1.x - h2f(h10)), l11 = f2h(v1.y - h2f(h11));
    uint2 uh, ul;
    uh.x = (uint32_t)h00 | ((uint32_t)h01 << 16);
    uh.y = (uint32_t)h10 | ((uint32_t)h11 << 16);
    ul.x = (uint32_t)l00 | ((uint32_t)l01 << 16);
    ul.y = (uint32_t)l10 | ((uint32_t)l11 << 16);
    g_Bfh[idx] = uh;
    g_Bfl[idx] = ul;
}

// ===========================================================================
// gS kernel: CTA 64(M) x 128(N), warp 32x32, acc 32 regs -> 3 CTAs/SM.
// A in smem (K-chunk 64, 3-stage), B direct from fragment gmem.
// grid (10, 128): n-tiles 0..7 -> dist; 8..9 -> P
// ===========================================================================
#define STAGE_S 16384
#define SMEM_S  (3 * STAGE_S)

__global__ void __launch_bounds__(256, 3) gS_kernel() {
    extern __shared__ char smem[];
    uint32_t sb0 = smem_to_u32(smem);
    float acc[2][4][4];
#pragma unroll
    for (int a_ = 0; a_ < 2; a_++)
#pragma unroll
        for (int b_ = 0; b_ < 4; b_++)
#pragma unroll
            for (int c_ = 0; c_ < 4; c_++) acc[a_][b_][c_] = 0.f;

    const int tid = threadIdx.x;
    const int lane = tid & 31, wid = tid >> 5;
    const int wm = (wid & 1) * 32, wn = (wid >> 1) * 32;
    const int m0 = blockIdx.y * 64, n0 = blockIdx.x * 128;
    const int bntile = (n0 + wn) >> 3;

    auto issueA = [&](int c, int s) {
        const int k0 = c * 64;
        const uint32_t sb = sb0 + s * STAGE_S;
#pragma unroll
        for (int t = 0; t < 2; t++) {
            int u = t * 256 + tid;
            int r = u >> 3, c8 = u & 7;
            uint32_t off = r * 128 + ((c8 ^ (r & 7)) << 4);
            cp16(sb + off,        g_sfhi + (size_t)(m0 + r) * D_DIM + k0 + c8 * 8);
            cp16(sb + off + 8192, g_sflo + (size_t)(m0 + r) * D_DIM + k0 + c8 * 8);
        }
        CP_COMMIT();
    };

    issueA(0, 0);
    issueA(1, 1);
    int s = 0;
    for (int c = 0; c < 4; c++) {
        if (c < 3) asm volatile("cp.async.wait_group 1;" ::: "memory");
        else       asm volatile("cp.async.wait_group 0;" ::: "memory");
        __syncthreads();
        if (c + 2 < 4) {
            int s2 = s + 2; if (s2 >= 3) s2 -= 3;
            issueA(c + 2, s2);
        }
        const uint32_t sb = sb0 + s * STAGE_S;
#pragma unroll
        for (int kq = 0; kq < 4; kq++) {
            uint32_t ah[2][4], al[2][4], bh[8], bl[8];
#pragma unroll
            for (int mt = 0; mt < 2; mt++) {
                int row = wm + mt * 16 + (lane & 15);
                int c8 = kq * 2 + (lane >> 4);
                uint32_t a = sb + row * 128 + ((c8 ^ (row & 7)) << 4);
                LDSM_X4(ah[mt], a);
                LDSM_X4(al[mt], a + 8192);
            }
#pragma unroll
            for (int n8 = 0; n8 < 4; n8++) {
                size_t bi = (((size_t)(bntile + n8) * 4 + c) * 4 + kq) * 32 + lane;
                uint2 h2 = g_Bfh[bi];
                uint2 l2 = g_Bfl[bi];
                bh[n8 * 2] = h2.x; bh[n8 * 2 + 1] = h2.y;
                bl[n8 * 2] = l2.x; bl[n8 * 2 + 1] = l2.y;
            }
#pragma unroll
            for (int mt = 0; mt < 2; mt++)
#pragma unroll
                for (int n8 = 0; n8 < 4; n8++)
                    mma16816(acc[mt][n8], ah[mt], bh + n8 * 2);
#pragma unroll
            for (int mt = 0; mt < 2; mt++)
#pragma unroll
                for (int n8 = 0; n8 < 4; n8++)
                    mma16816(acc[mt][n8], ah[mt], bl + n8 * 2);
#pragma unroll
            for (int mt = 0; mt < 2; mt++)
#pragma unroll
                for (int n8 = 0; n8 < 4; n8++)
                    mma16816(acc[mt][n8], al[mt], bh + n8 * 2);
        }
        s++; if (s >= 3) s -= 3;
        __syncthreads();
    }

    const int g = lane >> 2, t = lane & 3;
    if (blockIdx.x < 8) {
#pragma unroll
        for (int mt = 0; mt < 2; mt++)
#pragma unroll
            for (int n8 = 0; n8 < 4; n8++) {
                int col = n0 + wn + n8 * 8 + t * 2;
                float2 ec = *(const float2*)(g_ecoef + col);
#pragma unroll
                for (int h = 0; h < 2; h++) {
                    int m = m0 + wm + mt * 16 + g + h * 8;
                    float2 o;
                    o.x = ec.x - 2.f * acc[mt][n8][h * 2 + 0];
                    o.y = ec.y - 2.f * acc[mt][n8][h * 2 + 1];
                    *(float2*)(g_dist + (size_t)m * NC + col) = o;
                }
            }
    } else {
        const int p0 = (blockIdx.x - 8) * 128;
#pragma unroll
        for (int mt = 0; mt < 2; mt++)
#pragma unroll
            for (int n8 = 0; n8 < 4; n8++) {
                int col = p0 + wn + n8 * 8 + t * 2;
#pragma unroll
                for (int h = 0; h < 2; h++) {
                    int m = m0 + wm + mt * 16 + g + h * 8;
                    float2 o;
                    o.x = acc[mt][n8][h * 2 + 0];
                    o.y = acc[mt][n8][h * 2 + 1];
                    *(float2*)(g_P + (size_t)m * D_DIM + col) = o;
                }
            }
    }
}

// ===========================================================================
// rowz kernel: [0,1024) argmin+softmax+colsum+dmin+gather; [1024,2048) znorm.
// Last block computes final scalars.
// ===========================================================================
__global__ void __launch_bounds__(256) k_rowz(float* __restrict__ out_idx,
                                              const float* __restrict__ sf,
                                              const float* __restrict__ E,
                                              float* __restrict__ out) {
    const int bid = blockIdx.x;
    const int tid = threadIdx.x, lane = tid & 31, w = tid >> 5;
    if (bid >= 1024) {
        const int row = (bid - 1024) * 8 + w;
        const float4* s4 = (const float4*)(sf + (size_t)row * D_DIM);
        const float4* p4 = (const float4*)(g_P + (size_t)row * D_DIM);
        const float4* h4 = (const float4*)g_h;
        float acc = 0.f;
#pragma unroll
        for (int i = 0; i < 2; i++) {
            int j = lane + i * 32;
            float4 a = s4[j], p = p4[j], hh = h4[j];
            acc += a.x * (p.x + 2.f * hh.x) + a.y * (p.y + 2.f * hh.y)
                 + a.z * (p.z + 2.f * hh.z) + a.w * (p.w + 2.f * hh.w);
        }
        for (int o = 16; o > 0; o >>= 1) acc += __shfl_down_sync(0xffffffffu, acc, o);
        if (lane == 0) atomicAdd(&g_vqsum, acc + g_bnorm);
    } else {
        __shared__ float swv[8];
        __shared__ int   swi[8];
        __shared__ float s_min, s_sum;
        __shared__ int   sidx[8];
        float cs0 = 0.f, cs1 = 0.f, cs2 = 0.f, cs3 = 0.f;
        float dmin_sum = 0.f;
        const int r0 = bid * 8;
        for (int rr = 0; rr < 8; rr++) {
            const int row = r0 + rr;
            float4 v = ((const float4*)(g_dist + (size_t)row * NC))[tid];
            float vmin = v.x; int imin = tid * 4;
            if (v.y < vmin) { vmin = v.y; imin = tid * 4 + 1; }
            if (v.z < vmin) { vmin = v.z; imin = tid * 4 + 2; }
            if (v.w < vmin) { vmin = v.w; imin = tid * 4 + 3; }
            for (int o = 16; o > 0; o >>= 1) {
                float ov = __shfl_down_sync(0xffffffffu, vmin, o);
                int   oi = __shfl_down_sync(0xffffffffu, imin, o);
                if (ov < vmin || (ov == vmin && oi < imin)) { vmin = ov; imin = oi; }
            }
            if (lane == 0) { swv[w] = vmin; swi[w] = imin; }
            __syncthreads();
            if (w == 0) {
                vmin = (lane < 8) ? swv[lane] : 3.4e38f;
                imin = (lane < 8) ? swi[lane] : 0x7fffffff;
                for (int o = 4; o > 0; o >>= 1) {
                    float ov = __shfl_down_sync(0xffffffffu, vmin, o);
                    int   oi = __shfl_down_sync(0xffffffffu, imin, o);
                    if (ov < vmin || (ov == vmin && oi < imin)) { vmin = ov; imin = oi; }
                }
                if (lane == 0) {
                    s_min = vmin;
                    sidx[rr] = imin;
                    out_idx[row] = (float)imin;
                }
            }
            __syncthreads();
            const float mn = s_min;
            if (tid == 0) dmin_sum += mn;
            float e0 = expf(mn - v.x), e1 = expf(mn - v.y);
            float e2 = expf(mn - v.z), e3 = expf(mn - v.w);
            float ss = e0 + e1 + e2 + e3;
            for (int o = 16; o > 0; o >>= 1) ss += __shfl_down_sync(0xffffffffu, ss, o);
            if (lane == 0) swv[w] = ss;
            __syncthreads();
            if (w == 0) {
                ss = (lane < 8) ? swv[lane] : 0.f;
                for (int o = 4; o > 0; o >>= 1) ss += __shfl_down_sync(0xffffffffu, ss, o);
                if (lane == 0) s_sum = ss;
            }
            __syncthreads();
            const float inv = 1.f / s_sum;
            cs0 += e0 * inv; cs1 += e1 * inv; cs2 += e2 * inv; cs3 += e3 * inv;
            __syncthreads();
        }
        atomicAdd(&g_colsum[tid * 4 + 0], cs0);
        atomicAdd(&g_colsum[tid * 4 + 1], cs1);
        atomicAdd(&g_colsum[tid * 4 + 2], cs2);
        atomicAdd(&g_colsum[tid * 4 + 3], cs3);
        if (tid == 0) atomicAdd(&g_vqsum, dmin_sum);
        for (int rr = 0; rr < 8; rr++) {
            const float4* e4 = (const float4*)(E + (size_t)sidx[rr] * BD);
            float4* o4 = (float4*)(out + (size_t)(r0 + rr) * BD);
            for (int i = tid; i < BD / 4; i += 256) o4[i] = e4[i];
        }
    }

    // ---- last-block final scalars ----
    __shared__ unsigned int s_t;
    __threadfence();
    __syncthreads();
    if (tid == 0) s_t = atomicAdd(&g_ticket, 1u);
    __syncthreads();
    if (s_t == 2047u) {
        __threadfence();
        float t = 0.f;
#pragma unroll
        for (int i = 0; i < 4; i++) {
            float avg = g_colsum[tid + i * 256] * (1.0f / (float)M_TOT);
            t += -avg * logf(avg + EPS_ENT);
        }
        __shared__ float sw[8];
        for (int o = 16; o > 0; o >>= 1) t += __shfl_down_sync(0xffffffffu, t, o);
        if (lane == 0) sw[w] = t;
        __syncthreads();
        if (w == 0) {
            t = (lane < 8) ? sw[lane] : 0.f;
            for (int o = 4; o > 0; o >>= 1) t += __shfl_down_sync(0xffffffffu, t, o);
            if (lane == 0) {
                const size_t OFF = (size_t)M_TOT * BD + M_TOT;
                out[OFF]     = g_vqsum * (1.0f / ((float)M_TOT * (float)BD));
                out[OFF + 1] = t;
            }
        }
    }
}

// ---------------------------------------------------------------------------
extern "C" void kernel_launch(void* const* d_in, const int* in_sizes, int n_in,
                              void* d_out, int out_size) {
    const float* sf = (const float*)d_in[0];
    const float* W  = (const float*)d_in[1];
    const float* b  = (const float*)d_in[2];
    const float* E  = (const float*)d_in[3];
    float* out      = (float*)d_out;
    float* out_idx  = out + (size_t)M_TOT * BD;

    cudaFuncSetAttribute(gFG_kernel, cudaFuncAttributeMaxDynamicSharedMemorySize, SMEM_FG);
    cudaFuncSetAttribute(gS_kernel,  cudaFuncAttributeMaxDynamicSharedMemorySize, SMEM_S);

    k_prep<<<PREP_BLOCKS, 256>>>(E, b, sf, W);
    gFG_kernel<<<GFG_BLOCKS, 256, SMEM_FG>>>(W, b);
    k_splitFG<<<320, 256>>>();
    gS_kernel<<<dim3(10, 128), 256, SMEM_S>>>();
    k_rowz<<<2048, 256>>>(out_idx, sf, E, out);
}